// round 5
// baseline (speedup 1.0000x reference)
#include <cuda_runtime.h>
#include <float.h>

typedef unsigned long long U64;

// ---------------- scratch ----------------
__device__ float g_cand0[10 * 128 * 8 * 5];   // [target][spatialCTA][warp][5]
__device__ float g_cand1[5 * 64 * 8 * 5];     // [target][CTA][warp][5]
__device__ int   g_count;                     // zero-init; self-reset each replay

// ---------------- packed f32x2 helpers ----------------
__device__ __forceinline__ U64 add2(U64 a, U64 b) {
    U64 r; asm("add.rn.f32x2 %0, %1, %2;" : "=l"(r) : "l"(a), "l"(b)); return r;
}
__device__ __forceinline__ U64 pack2(float lo, float hi) {
    U64 r; asm("mov.b64 %0, {%1, %2};" : "=l"(r) : "f"(lo), "f"(hi)); return r;
}
__device__ __forceinline__ float2 unpack2(U64 v) {
    float lo, hi; asm("mov.b64 {%0, %1}, %2;" : "=f"(lo), "=f"(hi) : "l"(v));
    return make_float2(lo, hi);
}
#define ABS2_MASK 0x7FFFFFFF7FFFFFFFULL

// ---------------- sorted-5 insert + warp butterfly top-5 ----------------
__device__ __forceinline__ void ins5(float& a0, float& a1, float& a2, float& a3,
                                     float& a4, float v)
{
    if (v < a4) {
        a4 = v; float t;
        if (a4 < a3) { t = a3; a3 = a4; a4 = t; }
        if (a3 < a2) { t = a2; a2 = a3; a3 = t; }
        if (a2 < a1) { t = a1; a1 = a2; a2 = t; }
        if (a1 < a0) { t = a0; a0 = a1; a1 = t; }
    }
}

// After this, every lane holds the warp-wide 5 smallest (sorted).
__device__ __forceinline__ void warpTop5(float& a0, float& a1, float& a2,
                                         float& a3, float& a4)
{
#pragma unroll
    for (int m = 16; m >= 1; m >>= 1) {
        float b0 = __shfl_xor_sync(0xffffffffu, a0, m);
        float b1 = __shfl_xor_sync(0xffffffffu, a1, m);
        float b2 = __shfl_xor_sync(0xffffffffu, a2, m);
        float b3 = __shfl_xor_sync(0xffffffffu, a3, m);
        float b4 = __shfl_xor_sync(0xffffffffu, a4, m);
        ins5(a0, a1, a2, a3, a4, b0);
        ins5(a0, a1, a2, a3, a4, b1);
        ins5(a0, a1, a2, a3, a4, b2);
        ins5(a0, a1, a2, a3, a4, b3);
        ins5(a0, a1, a2, a3, a4, b4);
    }
}

// =====================================================================
// Single fused kernel. grid = (8, 16, 3), 256 threads.
//   z in {0,1}: scale0 (C=64,H=W=256,ps=3,Hm=253), 5 targets per z
//   z == 2   : scale1 (C=128,H=W=128,ps=1,Hm=127), flat CTA < 64
// 320 participating CTAs; last one (atomic) merges candidates -> out.
// =====================================================================
#define TILE_W 32
#define TILE_H 16
#define SM_W 34
#define SM_H 18
#define SM_N (SM_W * SM_H)   // 612
#define TPG 5
#define NCTA_PART 320

__global__ __launch_bounds__(256, 3) void fused_kernel(
    const float* __restrict__ src0, const float* __restrict__ tgt0,
    const int* __restrict__ pos0,
    const float* __restrict__ src1, const float* __restrict__ tgt1,
    const int* __restrict__ pos1,
    float* __restrict__ out)
{
    __shared__ __align__(16) U64 s_negt[32 * TPG * 10];   // [cp][T][10 pad]
    __shared__ U64 s_tile[2][SM_N];                       // double-buffered tile
    __shared__ float s_partial[15];
    __shared__ int s_last;

    const int tid  = threadIdx.x;
    const int wid  = tid >> 5;
    const int lane = tid & 31;

    if (blockIdx.z == 2) {
        // ------------------------- scale 1 -------------------------
        const int flat = blockIdx.y * 8 + blockIdx.x;
        if (flat >= 64) return;

        U64* negt1 = s_negt;                   // 320 U64 reused
        for (int i = tid; i < 64 * 5; i += 256) {
            int T = i % 5, cp = i / 5;
            int th = pos1[T * 2 + 0], tw = pos1[T * 2 + 1];
            const float* b = tgt1 + th * 128 + tw;
            negt1[i] = pack2(-b[(2 * cp) * 16384], -b[(2 * cp + 1) * 16384]);
        }
        __syncthreads();

        const int p  = flat * 256 + tid;
        const int pc = p < 16129 ? p : 16128;   // clamp; keep thread alive
        const int h = pc / 127, w = pc - h * 127;
        const float* sp = src1 + h * 128 + w;

        U64 acc[5];
#pragma unroll
        for (int T = 0; T < 5; T++) acc[T] = 0ULL;

        for (int cp = 0; cp < 64; cp++) {
            U64 s = pack2(sp[(2 * cp) * 16384], sp[(2 * cp + 1) * 16384]);
#pragma unroll
            for (int T = 0; T < 5; T++) {
                U64 d = add2(s, negt1[cp * 5 + T]) & ABS2_MASK;
                acc[T] = add2(acc[T], d);
            }
        }

#pragma unroll
        for (int T = 0; T < 5; T++) {
            float2 a = unpack2(acc[T]);
            float a0 = (p < 16129) ? (a.x + a.y) : FLT_MAX;
            float a1 = FLT_MAX, a2 = FLT_MAX, a3 = FLT_MAX, a4 = FLT_MAX;
            warpTop5(a0, a1, a2, a3, a4);
            if (lane == 0) {
                float* c = g_cand1 + ((T * 64 + flat) * 8 + wid) * 5;
                c[0] = a0; c[1] = a1; c[2] = a2; c[3] = a3; c[4] = a4;
            }
        }
    } else {
        // ------------------------- scale 0 -------------------------
        const int tx = blockIdx.x * TILE_W;
        const int ty = blockIdx.y * TILE_H;
        const int tb = blockIdx.z * TPG;
        const int sx = blockIdx.y * 8 + blockIdx.x;   // spatial CTA 0..127

        for (int i = tid; i < 32 * TPG * 9; i += 256) {
            int o  = i % 9;
            int T  = (i / 9) % TPG;
            int cp = i / (9 * TPG);
            int th = pos0[(tb + T) * 2 + 0];
            int tw = pos0[(tb + T) * 2 + 1];
            int di = o / 3, dj = o % 3;
            const float* b = tgt0 + (th + di) * 256 + (tw + dj);
            s_negt[cp * (TPG * 10) + T * 10 + o] =
                pack2(-b[(2 * cp) * 65536], -b[(2 * cp + 1) * 65536]);
        }

        int  goff[3];
        bool gval[3];
#pragma unroll
        for (int k = 0; k < 3; k++) {
            int i = tid + k * 256;
            int r = i / SM_W, c = i - r * SM_W;
            int y = ty + r, x = tx + c;
            gval[k] = (i < SM_N) && (y < 256) && (x < 256);
            goff[k] = y * 256 + x;
        }

        U64 pre[3];
        {   // prologue: cp = 0 -> buf 0
#pragma unroll
            for (int k = 0; k < 3; k++)
                pre[k] = gval[k] ? pack2(src0[goff[k]], src0[goff[k] + 65536]) : 0ULL;
#pragma unroll
            for (int k = 0; k < 3; k++) {
                int i = tid + k * 256;
                if (i < SM_N) s_tile[0][i] = pre[k];
            }
        }
        __syncthreads();

        const int thx = lane;
        const int thy = wid;
        const int w  = tx + thx;
        const int h0 = ty + 2 * thy;
        const bool act0 = (w < 253) && (h0 < 253);
        const bool act1 = (w < 253) && (h0 + 1 < 253);
        const int r0 = 2 * thy;

        U64 acc0[TPG], acc1[TPG];
#pragma unroll
        for (int T = 0; T < TPG; T++) { acc0[T] = 0ULL; acc1[T] = 0ULL; }

        for (int cp = 0; cp < 32; cp++) {
            if (cp + 1 < 32) {                       // prefetch next pair
                const float* s = src0 + (2 * (cp + 1)) * 65536;
#pragma unroll
                for (int k = 0; k < 3; k++)
                    pre[k] = gval[k] ? pack2(s[goff[k]], s[goff[k] + 65536]) : 0ULL;
            }

            const U64* buf = s_tile[cp & 1];
            U64 sv[4][3];
#pragma unroll
            for (int r = 0; r < 4; r++)
#pragma unroll
                for (int j = 0; j < 3; j++)
                    sv[r][j] = buf[(r0 + r) * SM_W + thx + j];

            const U64* tp = s_negt + cp * (TPG * 10);
#pragma unroll
            for (int T = 0; T < TPG; T++) {
                const ulonglong2* tp2 = (const ulonglong2*)(tp + T * 10);
#pragma unroll
                for (int o2 = 0; o2 < 4; o2++) {
                    ulonglong2 q = tp2[o2];
                    {
                        const int o = 2 * o2, di = o / 3, dj = o % 3;
                        U64 d0 = add2(sv[di][dj],     q.x) & ABS2_MASK;
                        U64 d1 = add2(sv[di + 1][dj], q.x) & ABS2_MASK;
                        acc0[T] = add2(acc0[T], d0);
                        acc1[T] = add2(acc1[T], d1);
                    }
                    {
                        const int o = 2 * o2 + 1, di = o / 3, dj = o % 3;
                        U64 d0 = add2(sv[di][dj],     q.y) & ABS2_MASK;
                        U64 d1 = add2(sv[di + 1][dj], q.y) & ABS2_MASK;
                        acc0[T] = add2(acc0[T], d0);
                        acc1[T] = add2(acc1[T], d1);
                    }
                }
                {   // o = 8
                    U64 nt = tp[T * 10 + 8];
                    U64 d0 = add2(sv[2][2], nt) & ABS2_MASK;
                    U64 d1 = add2(sv[3][2], nt) & ABS2_MASK;
                    acc0[T] = add2(acc0[T], d0);
                    acc1[T] = add2(acc1[T], d1);
                }
            }

            if (cp + 1 < 32) {
                U64* nb = s_tile[(cp + 1) & 1];
#pragma unroll
                for (int k = 0; k < 3; k++) {
                    int i = tid + k * 256;
                    if (i < SM_N) nb[i] = pre[k];
                }
                __syncthreads();
            }
        }

        // per-warp top-5 per target (no barriers)
#pragma unroll
        for (int T = 0; T < TPG; T++) {
            float2 A0 = unpack2(acc0[T]);
            float2 A1 = unpack2(acc1[T]);
            float v0 = act0 ? (A0.x + A0.y) : FLT_MAX;
            float v1 = act1 ? (A1.x + A1.y) : FLT_MAX;
            float a0 = fminf(v0, v1), a1 = fmaxf(v0, v1);
            float a2 = FLT_MAX, a3 = FLT_MAX, a4 = FLT_MAX;
            warpTop5(a0, a1, a2, a3, a4);
            if (lane == 0) {
                float* c = g_cand0 + (((tb + T) * 128 + sx) * 8 + wid) * 5;
                c[0] = a0; c[1] = a1; c[2] = a2; c[3] = a3; c[4] = a4;
            }
        }
    }

    // --------------- last-CTA merge + finalize ---------------
    if (tid == 0) {
        __threadfence();
        int old = atomicAdd(&g_count, 1);
        s_last = (old == NCTA_PART - 1);
        if (s_last) g_count = 0;             // reset for next graph replay
    }
    __syncthreads();
    if (!s_last) return;
    __threadfence();

    // warp w handles targets w and w+8 fully in-warp
    for (int t = wid; t < 15; t += 8) {
        const float* d; int n; float scale;
        if (t < 10) { d = g_cand0 + t * 5120;        n = 5120; scale = 1.0f / 28800.0f; }
        else        { d = g_cand1 + (t - 10) * 2560; n = 2560; scale = 1.0f / 6400.0f; }

        float a0 = FLT_MAX, a1 = FLT_MAX, a2 = FLT_MAX, a3 = FLT_MAX, a4 = FLT_MAX;
        for (int i = lane; i < n; i += 32)
            ins5(a0, a1, a2, a3, a4, __ldcg(d + i));
        warpTop5(a0, a1, a2, a3, a4);
        if (lane == 0)
            s_partial[t] = (a0 + a1 + a2 + a3 + a4) * scale;
    }
    __syncthreads();
    if (tid == 0) {
        float s = 0.f;
#pragma unroll
        for (int i = 0; i < 15; i++) s += s_partial[i];
        out[0] = s;
    }
}

// =====================================================================
extern "C" void kernel_launch(void* const* d_in, const int* in_sizes, int n_in,
                              void* d_out, int out_size)
{
    const float* src0 = (const float*)d_in[0];
    const float* tgt0 = (const float*)d_in[1];
    const float* src1 = (const float*)d_in[2];
    const float* tgt1 = (const float*)d_in[3];
    const int*   pos0 = (const int*)d_in[4];
    const int*   pos1 = (const int*)d_in[5];

    dim3 g(8, 16, 3);
    fused_kernel<<<g, 256>>>(src0, tgt0, pos0, src1, tgt1, pos1, (float*)d_out);
}

// round 6
// speedup vs baseline: 2.5876x; 2.5876x over previous
#include <cuda_runtime.h>
#include <float.h>

typedef unsigned long long U64;

// ---------------- scratch ----------------
#define D0_STRIDE 64012   // 64009 padded to mult of 4
#define D1_STRIDE 16132   // 16129 padded
__device__ float g_dist0[10 * D0_STRIDE];
__device__ float g_dist1[5 * D1_STRIDE];
__device__ float g_cand[180 * 5];
__device__ int   g_count;              // zero-init; self-reset each replay

// ---------------- packed f32x2 helpers ----------------
__device__ __forceinline__ U64 add2(U64 a, U64 b) {
    U64 r; asm("add.rn.f32x2 %0, %1, %2;" : "=l"(r) : "l"(a), "l"(b)); return r;
}
__device__ __forceinline__ U64 pack2(float lo, float hi) {
    U64 r; asm("mov.b64 %0, {%1, %2};" : "=l"(r) : "f"(lo), "f"(hi)); return r;
}
__device__ __forceinline__ float2 unpack2(U64 v) {
    float lo, hi; asm("mov.b64 {%0, %1}, %2;" : "=f"(lo), "=f"(hi) : "l"(v));
    return make_float2(lo, hi);
}
#define ABS2_MASK 0x7FFFFFFF7FFFFFFFULL

// =====================================================================
// dist kernel: EXACT round-2 structure (known 44us core).
//   grid = (8, 16, 3), 256 threads
//   z in {0,1}: scale0 (C=64,H=W=256,ps=3,Hm=253), 5 targets per z
//   z == 2   : scale1 (C=128,H=W=128,ps=1,Hm=127), flat CTA < 64
// =====================================================================
#define TILE_W 32
#define TILE_H 16
#define SM_W 34
#define SM_H 18
#define SM_N (SM_W * SM_H)   // 612
#define TPG 5

__global__ __launch_bounds__(256, 3) void dist_kernel(
    const float* __restrict__ src0, const float* __restrict__ tgt0,
    const int* __restrict__ pos0,
    const float* __restrict__ src1, const float* __restrict__ tgt1,
    const int* __restrict__ pos1)
{
    __shared__ U64 s_negt[32 * TPG * 10];        // padded [cp][T][10]
    __shared__ U64 s_tile[2][SM_N];              // double-buffered tile

    const int tid = threadIdx.x;

    // ---------------- scale-1 branch ----------------
    if (blockIdx.z == 2) {
        const int flat = blockIdx.y * 8 + blockIdx.x;
        if (flat >= 64) return;
        U64* negt1 = s_negt;
        for (int i = tid; i < 64 * 5; i += 256) {
            int T = i % 5, cp = i / 5;
            int th = pos1[T * 2 + 0], tw = pos1[T * 2 + 1];
            const float* b = tgt1 + th * 128 + tw;
            negt1[i] = pack2(-b[(2 * cp) * 16384], -b[(2 * cp + 1) * 16384]);
        }
        __syncthreads();

        const int p = blockIdx.y; // unused dummy to keep structure minimal
        (void)p;
        const int pp = flat * 256 + tid;
        if (pp >= 16129) return;
        const int h = pp / 127, w = pp - h * 127;
        const float* sp = src1 + h * 128 + w;

        U64 acc[5];
#pragma unroll
        for (int T = 0; T < 5; T++) acc[T] = 0ULL;

        for (int cp = 0; cp < 64; cp++) {
            U64 s = pack2(sp[(2 * cp) * 16384], sp[(2 * cp + 1) * 16384]);
#pragma unroll
            for (int T = 0; T < 5; T++) {
                U64 d = add2(s, negt1[cp * 5 + T]) & ABS2_MASK;
                acc[T] = add2(acc[T], d);
            }
        }
#pragma unroll
        for (int T = 0; T < 5; T++) {
            float2 a = unpack2(acc[T]);
            g_dist1[T * D1_STRIDE + pp] = a.x + a.y;
        }
        return;
    }

    // ---------------- scale-0 branch ----------------
    const int tx = blockIdx.x * TILE_W;
    const int ty = blockIdx.y * TILE_H;
    const int tb = blockIdx.z * TPG;

    for (int i = tid; i < 32 * TPG * 9; i += 256) {
        int o  = i % 9;
        int T  = (i / 9) % TPG;
        int cp = i / (9 * TPG);
        int th = pos0[(tb + T) * 2 + 0];
        int tw = pos0[(tb + T) * 2 + 1];
        int di = o / 3, dj = o % 3;
        const float* b = tgt0 + (th + di) * 256 + (tw + dj);
        s_negt[cp * (TPG * 10) + T * 10 + o] =
            pack2(-b[(2 * cp) * 65536], -b[(2 * cp + 1) * 65536]);
    }

    int  goff[3];
    bool gval[3];
#pragma unroll
    for (int k = 0; k < 3; k++) {
        int i = tid + k * 256;
        int r = i / SM_W, c = i - r * SM_W;
        int y = ty + r, x = tx + c;
        gval[k] = (i < SM_N) && (y < 256) && (x < 256);
        goff[k] = y * 256 + x;
    }

    U64 pre[3];
    {   // prologue: cp = 0 -> buf 0
#pragma unroll
        for (int k = 0; k < 3; k++)
            pre[k] = gval[k] ? pack2(src0[goff[k]], src0[goff[k] + 65536]) : 0ULL;
#pragma unroll
        for (int k = 0; k < 3; k++) {
            int i = tid + k * 256;
            if (i < SM_N) s_tile[0][i] = pre[k];
        }
    }
    __syncthreads();

    const int thx = tid & 31;
    const int thy = tid >> 5;
    const int w  = tx + thx;
    const int h0 = ty + 2 * thy;
    const bool act0 = (w < 253) && (h0 < 253);
    const bool act1 = (w < 253) && (h0 + 1 < 253);
    const int r0 = 2 * thy;

    U64 acc0[TPG], acc1[TPG];
#pragma unroll
    for (int T = 0; T < TPG; T++) { acc0[T] = 0ULL; acc1[T] = 0ULL; }

    for (int cp = 0; cp < 32; cp++) {
        if (cp + 1 < 32) {
            const float* s = src0 + (2 * (cp + 1)) * 65536;
#pragma unroll
            for (int k = 0; k < 3; k++)
                pre[k] = gval[k] ? pack2(s[goff[k]], s[goff[k] + 65536]) : 0ULL;
        }

        const U64* buf = s_tile[cp & 1];
        U64 sv[4][3];
#pragma unroll
        for (int r = 0; r < 4; r++)
#pragma unroll
            for (int j = 0; j < 3; j++)
                sv[r][j] = buf[(r0 + r) * SM_W + thx + j];

        const U64* tp = s_negt + cp * (TPG * 10);
#pragma unroll
        for (int T = 0; T < TPG; T++) {
            const ulonglong2* tp2 = (const ulonglong2*)(tp + T * 10);
#pragma unroll
            for (int o2 = 0; o2 < 4; o2++) {
                ulonglong2 q = tp2[o2];
                {
                    const int o = 2 * o2, di = o / 3, dj = o % 3;
                    U64 d0 = add2(sv[di][dj],     q.x) & ABS2_MASK;
                    U64 d1 = add2(sv[di + 1][dj], q.x) & ABS2_MASK;
                    acc0[T] = add2(acc0[T], d0);
                    acc1[T] = add2(acc1[T], d1);
                }
                {
                    const int o = 2 * o2 + 1, di = o / 3, dj = o % 3;
                    U64 d0 = add2(sv[di][dj],     q.y) & ABS2_MASK;
                    U64 d1 = add2(sv[di + 1][dj], q.y) & ABS2_MASK;
                    acc0[T] = add2(acc0[T], d0);
                    acc1[T] = add2(acc1[T], d1);
                }
            }
            {   // o = 8
                U64 nt = tp[T * 10 + 8];
                U64 d0 = add2(sv[2][2], nt) & ABS2_MASK;
                U64 d1 = add2(sv[3][2], nt) & ABS2_MASK;
                acc0[T] = add2(acc0[T], d0);
                acc1[T] = add2(acc1[T], d1);
            }
        }

        if (cp + 1 < 32) {
            U64* nb = s_tile[(cp + 1) & 1];
#pragma unroll
            for (int k = 0; k < 3; k++) {
                int i = tid + k * 256;
                if (i < SM_N) nb[i] = pre[k];
            }
            __syncthreads();
        }
    }

#pragma unroll
    for (int T = 0; T < TPG; T++) {
        float2 a0 = unpack2(acc0[T]);
        float2 a1 = unpack2(acc1[T]);
        if (act0) g_dist0[(tb + T) * D0_STRIDE + h0 * 253 + w]       = a0.x + a0.y;
        if (act1) g_dist0[(tb + T) * D0_STRIDE + (h0 + 1) * 253 + w] = a1.x + a1.y;
    }
}

// =====================================================================
// topk: 180 CTAs x 256 threads. bx<160: (t = bx/16, 16 chunks) over dist0.
// bx>=160: (t = 10 + (bx-160)/4, 4 chunks) over dist1. Per-CTA top5 ->
// g_cand[bx*5]. Last CTA merges all candidates and writes the scalar.
// =====================================================================
__device__ __forceinline__ void ins5(float& a0, float& a1, float& a2, float& a3,
                                     float& a4, float v)
{
    if (v < a4) {
        a4 = v; float t;
        if (a4 < a3) { t = a3; a3 = a4; a4 = t; }
        if (a3 < a2) { t = a2; a2 = a3; a3 = t; }
        if (a2 < a1) { t = a1; a1 = a2; a2 = t; }
        if (a1 < a0) { t = a0; a0 = a1; a1 = t; }
    }
}

__device__ __forceinline__ void warpTop5(float& a0, float& a1, float& a2,
                                         float& a3, float& a4)
{
#pragma unroll
    for (int m = 16; m >= 1; m >>= 1) {
        float b0 = __shfl_xor_sync(0xffffffffu, a0, m);
        float b1 = __shfl_xor_sync(0xffffffffu, a1, m);
        float b2 = __shfl_xor_sync(0xffffffffu, a2, m);
        float b3 = __shfl_xor_sync(0xffffffffu, a3, m);
        float b4 = __shfl_xor_sync(0xffffffffu, a4, m);
        ins5(a0, a1, a2, a3, a4, b0);
        ins5(a0, a1, a2, a3, a4, b1);
        ins5(a0, a1, a2, a3, a4, b2);
        ins5(a0, a1, a2, a3, a4, b3);
        ins5(a0, a1, a2, a3, a4, b4);
    }
}

#define NCTA_TOPK 180

__global__ __launch_bounds__(256) void topk_kernel(float* __restrict__ out)
{
    __shared__ float s_warp[8 * 5];
    __shared__ float s_partial[15];
    __shared__ int   s_last;

    const int bx   = blockIdx.x;
    const int tid  = threadIdx.x;
    const int wid  = tid >> 5;
    const int lane = tid & 31;

    const float* d;
    int n, nchunks, chunk;
    if (bx < 160) { int t = bx >> 4; chunk = bx & 15; nchunks = 16;
                    d = g_dist0 + t * D0_STRIDE; n = 64009; }
    else          { int t = (bx - 160) >> 2; chunk = (bx - 160) & 3; nchunks = 4;
                    d = g_dist1 + t * D1_STRIDE; n = 16129; }

    const int n4  = n >> 2;                          // full float4 groups
    const int gpc = (n4 + nchunks - 1) / nchunks;
    const int g0  = chunk * gpc;
    const int g1  = min(n4, g0 + gpc);
    const float4* d4 = (const float4*)d;

    float a0 = FLT_MAX, a1 = FLT_MAX, a2 = FLT_MAX, a3 = FLT_MAX, a4 = FLT_MAX;
    for (int i = g0 + tid; i < g1; i += 256) {
        float4 v = d4[i];
        ins5(a0, a1, a2, a3, a4, v.x);
        ins5(a0, a1, a2, a3, a4, v.y);
        ins5(a0, a1, a2, a3, a4, v.z);
        ins5(a0, a1, a2, a3, a4, v.w);
    }
    if (chunk == 0 && tid == 0)                      // tail (n % 4 == 1)
        for (int i = n4 * 4; i < n; i++) ins5(a0, a1, a2, a3, a4, d[i]);

    warpTop5(a0, a1, a2, a3, a4);
    if (lane < 5) {
        float v = (lane == 0) ? a0 : (lane == 1) ? a1 : (lane == 2) ? a2
                 : (lane == 3) ? a3 : a4;
        s_warp[wid * 5 + lane] = v;
    }
    __syncthreads();
    if (wid == 0) {
        float b0 = (lane < 40) ? s_warp[lane] : FLT_MAX;
        a0 = b0; a1 = FLT_MAX; a2 = FLT_MAX; a3 = FLT_MAX; a4 = FLT_MAX;
        float b1 = (lane + 32 < 40) ? s_warp[lane + 32] : FLT_MAX;
        ins5(a0, a1, a2, a3, a4, b1);
        warpTop5(a0, a1, a2, a3, a4);
        if (lane == 0) {
            float* c = g_cand + bx * 5;
            c[0] = a0; c[1] = a1; c[2] = a2; c[3] = a3; c[4] = a4;
        }
    }

    // ---------------- last-CTA merge ----------------
    if (tid == 0) {
        __threadfence();
        int old = atomicAdd(&g_count, 1);
        s_last = (old == NCTA_TOPK - 1);
        if (s_last) g_count = 0;                    // reset for next replay
    }
    __syncthreads();
    if (!s_last) return;
    __threadfence();

    // warp w handles targets w and w+8
    for (int t = wid; t < 15; t += 8) {
        const float* c; int n2; float scale;
        if (t < 10) { c = g_cand + t * 80;              n2 = 80; scale = 1.0f / 28800.0f; }
        else        { c = g_cand + 800 + (t - 10) * 20; n2 = 20; scale = 1.0f / 6400.0f; }

        float m0 = FLT_MAX, m1 = FLT_MAX, m2 = FLT_MAX, m3 = FLT_MAX, m4 = FLT_MAX;
        for (int i = lane; i < n2; i += 32)
            ins5(m0, m1, m2, m3, m4, __ldcg(c + i));
        warpTop5(m0, m1, m2, m3, m4);
        if (lane == 0)
            s_partial[t] = (m0 + m1 + m2 + m3 + m4) * scale;
    }
    __syncthreads();
    if (tid == 0) {
        float s = 0.f;
#pragma unroll
        for (int i = 0; i < 15; i++) s += s_partial[i];
        out[0] = s;
    }
}

// =====================================================================
extern "C" void kernel_launch(void* const* d_in, const int* in_sizes, int n_in,
                              void* d_out, int out_size)
{
    const float* src0 = (const float*)d_in[0];
    const float* tgt0 = (const float*)d_in[1];
    const float* src1 = (const float*)d_in[2];
    const float* tgt1 = (const float*)d_in[3];
    const int*   pos0 = (const int*)d_in[4];
    const int*   pos1 = (const int*)d_in[5];

    dim3 g(8, 16, 3);
    dist_kernel<<<g, 256>>>(src0, tgt0, pos0, src1, tgt1, pos1);
    topk_kernel<<<NCTA_TOPK, 256>>>((float*)d_out);
}